// round 9
// baseline (speedup 1.0000x reference)
#include <cuda_runtime.h>

// TAHE: masked cosine-similarity weighted pooling (two-phase).
// out[b,d] = sum_l [ts[b,l]>0] * (cos(cur_n[b], rec[b,l]) + 1)/2 * items[b,l,d]
// B=4096, L=200, D=128 f32. HBM-bound; ~50% rows masked -> skipped loads.
// Phase 1: weights w[l] into smem (reads rec, half-warp per row, independent iters).
//          NOTE: half-warps may diverge on the mask -> width-16 shuffles MUST use
//          the half-warp member mask (0xffff << 16*half), not 0xffffffff.
// Phase 2: pure streaming accumulate of items with smem weights (deep MLP, no shfl).

#define TB 4096
#define TL 200
#define TD 128
#define WARPS 8
#define TEPS 1e-12f

__global__ __launch_bounds__(WARPS * 32, 1)
void tahe_kernel(const float* __restrict__ rec,
                 const float* __restrict__ cur,
                 const int*   __restrict__ ts,
                 const float* __restrict__ items,
                 float*       __restrict__ out)
{
    const int b      = blockIdx.x;
    const int wid    = threadIdx.x >> 5;
    const int lane   = threadIdx.x & 31;
    const int half   = lane >> 4;          // 0/1: which row of the pair
    const int lane16 = lane & 15;
    const unsigned hmask = 0xffffu << (half * 16);  // this half-warp's member mask

    __shared__ float  wbuf[TL];
    __shared__ float4 red[WARPS][32];

    // ---- normalize cur[b,:] (redundant per warp; 2KB, L1-resident) ----
    const float4* cur4 = reinterpret_cast<const float4*>(cur + (size_t)b * TD);
    float4 c = __ldg(&cur4[lane]);
    float ss = c.x * c.x + c.y * c.y + c.z * c.z + c.w * c.w;
    #pragma unroll
    for (int o = 16; o > 0; o >>= 1)
        ss += __shfl_xor_sync(0xffffffffu, ss, o);
    const float rn = rsqrtf(fmaxf(ss, TEPS));
    c.x *= rn; c.y *= rn; c.z *= rn; c.w *= rn;

    const float4* rec4 = reinterpret_cast<const float4*>(rec   + (size_t)b * TL * TD);
    const float4* it4  = reinterpret_cast<const float4*>(items + (size_t)b * TL * TD);
    const int*    tsb  = ts + (size_t)b * TL;

    // cur components this lane16 needs for its 2 float4s (indices 2*lane16, 2*lane16+1).
    // Full-warp shuffles, executed unconditionally by all 32 lanes.
    float4 c0, c1;
    {
        const int s0 = 2 * lane16;
        const int s1 = 2 * lane16 + 1;
        c0.x = __shfl_sync(0xffffffffu, c.x, s0);
        c0.y = __shfl_sync(0xffffffffu, c.y, s0);
        c0.z = __shfl_sync(0xffffffffu, c.z, s0);
        c0.w = __shfl_sync(0xffffffffu, c.w, s0);
        c1.x = __shfl_sync(0xffffffffu, c.x, s1);
        c1.y = __shfl_sync(0xffffffffu, c.y, s1);
        c1.z = __shfl_sync(0xffffffffu, c.z, s1);
        c1.w = __shfl_sync(0xffffffffu, c.w, s1);
    }

    // ---- Phase 1: weights. Half-warp h = wid*2+half owns rows l = h, h+16, ... ----
    const int h = wid * 2 + half;
    for (int l = h; l < TL; l += 2 * WARPS) {
        const int m = __ldg(&tsb[l]);
        float w = 0.0f;
        if (m > 0) {
            const float4 r0 = __ldg(&rec4[l * 32 + 2 * lane16]);
            const float4 r1 = __ldg(&rec4[l * 32 + 2 * lane16 + 1]);
            float dot = r0.x * c0.x + r0.y * c0.y + r0.z * c0.z + r0.w * c0.w
                      + r1.x * c1.x + r1.y * c1.y + r1.z * c1.z + r1.w * c1.w;
            float sq  = r0.x * r0.x + r0.y * r0.y + r0.z * r0.z + r0.w * r0.w
                      + r1.x * r1.x + r1.y * r1.y + r1.z * r1.z + r1.w * r1.w;
            #pragma unroll
            for (int o = 8; o > 0; o >>= 1) {
                dot += __shfl_xor_sync(hmask, dot, o, 16);
                sq  += __shfl_xor_sync(hmask, sq,  o, 16);
            }
            const float sim = dot * rsqrtf(fmaxf(sq, TEPS));
            w = (sim + 1.0f) * 0.5f;
        }
        if (lane16 == 0) wbuf[l] = w;
    }
    __syncthreads();

    // ---- Phase 2: streaming accumulate. Warp owns l = wid, wid+8, ... ----
    float4 acc = make_float4(0.f, 0.f, 0.f, 0.f);
    #pragma unroll 4
    for (int l = wid; l < TL; l += WARPS) {
        const float w = wbuf[l];
        if (w != 0.0f) {
            const float4 v = __ldg(&it4[l * 32 + lane]);
            acc.x += w * v.x;
            acc.y += w * v.y;
            acc.z += w * v.z;
            acc.w += w * v.w;
        }
    }

    // ---- cross-warp reduction ----
    red[wid][lane] = acc;
    __syncthreads();

    if (wid == 0) {
        float4 s = red[0][lane];
        #pragma unroll
        for (int w = 1; w < WARPS; ++w) {
            const float4 t = red[w][lane];
            s.x += t.x; s.y += t.y; s.z += t.z; s.w += t.w;
        }
        reinterpret_cast<float4*>(out + (size_t)b * TD)[lane] = s;
    }
}

extern "C" void kernel_launch(void* const* d_in, const int* in_sizes, int n_in,
                              void* d_out, int out_size)
{
    const float* rec   = (const float*)d_in[0]; // recentTimeRepresentations [B,L,D]
    const float* cur   = (const float*)d_in[1]; // curTimeRepresentation    [B,D]
    const int*   ts    = (const int*)  d_in[2]; // recentTimestamps         [B,L]
    const float* items = (const float*)d_in[3]; // recentItemEmbeddings     [B,L,D]
    float*       out   = (float*)d_out;         // [B,D]

    tahe_kernel<<<TB, WARPS * 32>>>(rec, cur, ts, items, out);
}

// round 14
// speedup vs baseline: 1.2077x; 1.2077x over previous
#include <cuda_runtime.h>

// TAHE: masked cosine-similarity weighted pooling, fused single-pass (R3 structure)
// with: smem-preloaded mask row, x2 unroll (4 interleaved shfl chains, MLP_p1=4),
// unconditional shuffles (no member-mask hazards), conditional loads (skip masked rows).
// out[b,d] = sum_l [ts[b,l]>0] * (cos(cur_n[b], rec[b,l]) + 1)/2 * items[b,l,d]
// B=4096, L=200, D=128 f32. HBM-bound; ~50% rows masked.

#define TB 4096
#define TL 200
#define TD 128
#define WARPS 8
#define TEPS 1e-12f

__global__ __launch_bounds__(WARPS * 32, 1)
void tahe_kernel(const float* __restrict__ rec,
                 const float* __restrict__ cur,
                 const int*   __restrict__ ts,
                 const float* __restrict__ items,
                 float*       __restrict__ out)
{
    const int b    = blockIdx.x;
    const int tid  = threadIdx.x;
    const int wid  = tid >> 5;
    const int lane = tid & 31;

    __shared__ int    tss[TL];
    __shared__ float4 red[WARPS][32];

    // ---- preload mask row into smem (one coalesced pass) ----
    if (tid < TL) tss[tid] = __ldg(&ts[(size_t)b * TL + tid]);

    // ---- normalize cur[b,:] (redundant per warp; 2KB, L1-resident) ----
    const float4* cur4 = reinterpret_cast<const float4*>(cur + (size_t)b * TD);
    float4 c = __ldg(&cur4[lane]);
    float ss = c.x * c.x + c.y * c.y + c.z * c.z + c.w * c.w;
    #pragma unroll
    for (int o = 16; o > 0; o >>= 1)
        ss += __shfl_xor_sync(0xffffffffu, ss, o);
    const float rn = rsqrtf(fmaxf(ss, TEPS));
    c.x *= rn; c.y *= rn; c.z *= rn; c.w *= rn;

    __syncthreads();

    const float4* rec4 = reinterpret_cast<const float4*>(rec   + (size_t)b * TL * TD);
    const float4* it4  = reinterpret_cast<const float4*>(items + (size_t)b * TL * TD);

    float4 acc = make_float4(0.f, 0.f, 0.f, 0.f);

    // ---- mainloop: warp handles row pair (l0, l0+1); pairs strided by 16 ----
    // l0 = 2*wid + 16k covers every even l < 200; l0+1 <= 199 always.
    for (int l0 = 2 * wid; l0 < TL; l0 += 2 * WARPS) {
        const int l1 = l0 + 1;
        const int m0 = tss[l0];
        const int m1 = tss[l1];

        float4 r0 = make_float4(0.f, 0.f, 0.f, 0.f);
        float4 r1 = make_float4(0.f, 0.f, 0.f, 0.f);
        float4 v0 = make_float4(0.f, 0.f, 0.f, 0.f);
        float4 v1 = make_float4(0.f, 0.f, 0.f, 0.f);

        if (m0 > 0) {
            r0 = __ldg(&rec4[l0 * 32 + lane]);
            v0 = __ldg(&it4 [l0 * 32 + lane]);
        }
        if (m1 > 0) {
            r1 = __ldg(&rec4[l1 * 32 + lane]);
            v1 = __ldg(&it4 [l1 * 32 + lane]);
        }

        float dot0 = r0.x * c.x + r0.y * c.y + r0.z * c.z + r0.w * c.w;
        float sq0  = r0.x * r0.x + r0.y * r0.y + r0.z * r0.z + r0.w * r0.w;
        float dot1 = r1.x * c.x + r1.y * c.y + r1.z * c.z + r1.w * c.w;
        float sq1  = r1.x * r1.x + r1.y * r1.y + r1.z * r1.z + r1.w * r1.w;

        // 4 independent reduction chains, unconditional, full warp.
        #pragma unroll
        for (int o = 16; o > 0; o >>= 1) {
            dot0 += __shfl_xor_sync(0xffffffffu, dot0, o);
            sq0  += __shfl_xor_sync(0xffffffffu, sq0,  o);
            dot1 += __shfl_xor_sync(0xffffffffu, dot1, o);
            sq1  += __shfl_xor_sync(0xffffffffu, sq1,  o);
        }

        const float w0 = (m0 > 0) ? (dot0 * rsqrtf(fmaxf(sq0, TEPS)) + 1.0f) * 0.5f : 0.0f;
        const float w1 = (m1 > 0) ? (dot1 * rsqrtf(fmaxf(sq1, TEPS)) + 1.0f) * 0.5f : 0.0f;

        acc.x += w0 * v0.x + w1 * v1.x;
        acc.y += w0 * v0.y + w1 * v1.y;
        acc.z += w0 * v0.z + w1 * v1.z;
        acc.w += w0 * v0.w + w1 * v1.w;
    }

    // ---- cross-warp reduction of per-lane float4 partials ----
    red[wid][lane] = acc;
    __syncthreads();

    if (wid == 0) {
        float4 s = red[0][lane];
        #pragma unroll
        for (int w = 1; w < WARPS; ++w) {
            const float4 t = red[w][lane];
            s.x += t.x; s.y += t.y; s.z += t.z; s.w += t.w;
        }
        reinterpret_cast<float4*>(out + (size_t)b * TD)[lane] = s;
    }
}

extern "C" void kernel_launch(void* const* d_in, const int* in_sizes, int n_in,
                              void* d_out, int out_size)
{
    const float* rec   = (const float*)d_in[0]; // recentTimeRepresentations [B,L,D]
    const float* cur   = (const float*)d_in[1]; // curTimeRepresentation    [B,D]
    const int*   ts    = (const int*)  d_in[2]; // recentTimestamps         [B,L]
    const float* items = (const float*)d_in[3]; // recentItemEmbeddings     [B,L,D]
    float*       out   = (float*)d_out;         // [B,D]

    tahe_kernel<<<TB, WARPS * 32>>>(rec, cur, ts, items, out);
}